// round 13
// baseline (speedup 1.0000x reference)
#include <cuda_runtime.h>
#include <cuda_fp16.h>
#include <cstdint>

#define N_NODES 50000
#define N_EDGES 800000
#define DIM 128
#define NBS ((N_NODES + 255) / 256)   // 196 scan blocks

// ---------------- device scratch (no allocations allowed) ----------------
__device__ float  g_deg[N_NODES];
__device__ float  g_dis[N_NODES];
__device__ int    g_cnt[N_NODES];
__device__ int    g_pre[N_NODES];
__device__ int    g_bsum[NBS];
__device__ int    g_rowoff[N_NODES + 1];
__device__ int    g_cursor[N_NODES];
__device__ int    g_eid[N_EDGES];
__device__ __half g_h[N_NODES * DIM];   // GEMM output / agg gather buffer (fp16)
__device__ float  g_t[N_NODES * DIM];   // layer-1 output (fp32)

// ---------------- setup kernels ----------------
__global__ void init_kernel() {
    int i = blockIdx.x * blockDim.x + threadIdx.x;
    if (i < N_NODES) { g_deg[i] = 0.f; g_cnt[i] = 0; }
}

// 4 edges per thread: MLP=4 on the dst loads + atomics
__global__ void count_kernel(const int* __restrict__ ei,
                             const float* __restrict__ ew) {
    int e4 = blockIdx.x * blockDim.x + threadIdx.x;
    if (e4 < N_EDGES / 4) {
        int4   d = *(const int4*)(ei + N_EDGES + e4 * 4);
        float4 w = *(const float4*)(ew + e4 * 4);
        atomicAdd(&g_deg[d.x], w.x); atomicAdd(&g_cnt[d.x], 1);
        atomicAdd(&g_deg[d.y], w.y); atomicAdd(&g_cnt[d.y], 1);
        atomicAdd(&g_deg[d.z], w.z); atomicAdd(&g_cnt[d.z], 1);
        atomicAdd(&g_deg[d.w], w.w); atomicAdd(&g_cnt[d.w], 1);
    }
}

__device__ __forceinline__ int block_scan_incl(int v, int* ws) {
    const int lane = threadIdx.x & 31;
    const int w = threadIdx.x >> 5;
    int incl = v;
    #pragma unroll
    for (int o = 1; o < 32; o <<= 1) {
        int t = __shfl_up_sync(0xffffffffu, incl, o);
        if (lane >= o) incl += t;
    }
    if (lane == 31) ws[w] = incl;
    __syncthreads();
    if (w == 0) {
        int nw = blockDim.x >> 5;
        int s = (lane < nw) ? ws[lane] : 0;
        #pragma unroll
        for (int o = 1; o < 32; o <<= 1) {
            int t = __shfl_up_sync(0xffffffffu, s, o);
            if (lane >= o) s += t;
        }
        if (lane < nw) ws[lane] = s;
    }
    __syncthreads();
    if (w > 0) incl += ws[w - 1];
    return incl;
}

// pass 1: per-block exclusive pre-scan + block sums; fused dis = rsqrt(deg+1)
__global__ __launch_bounds__(256) void scan1_kernel() {
    __shared__ int ws[8];
    int i = blockIdx.x * 256 + threadIdx.x;
    int v = (i < N_NODES) ? g_cnt[i] : 0;
    int incl = block_scan_incl(v, ws);
    if (i < N_NODES) g_pre[i] = incl - v;
    if (threadIdx.x == 255) g_bsum[blockIdx.x] = incl;
    if (i < N_NODES) g_dis[i] = rsqrtf(g_deg[i] + 1.0f);
}

// pass 2 (merged): each block computes its own offset from g_bsum, applies it
__global__ __launch_bounds__(256) void scan3_kernel() {
    __shared__ int s_off;
    const int b = blockIdx.x;
    const int t = threadIdx.x;
    if (t < 32) {
        int sum = 0;
        for (int j = t; j < b; j += 32) sum += g_bsum[j];
        #pragma unroll
        for (int o = 16; o > 0; o >>= 1)
            sum += __shfl_down_sync(0xffffffffu, sum, o);
        if (t == 0) s_off = sum;
    }
    __syncthreads();
    int i = b * 256 + t;
    if (i < N_NODES) {
        int r = g_pre[i] + s_off;
        g_rowoff[i] = r;
        g_cursor[i] = r;
    }
    if (i == 0) g_rowoff[N_NODES] = N_EDGES;
}

// 4 edges per thread: MLP=4 on the cursor atomics
__global__ void fill_kernel(const int* __restrict__ ei) {
    int e4 = blockIdx.x * blockDim.x + threadIdx.x;
    if (e4 < N_EDGES / 4) {
        int e = e4 * 4;
        int4 d = *(const int4*)(ei + N_EDGES + e);
        int p0 = atomicAdd(&g_cursor[d.x], 1);
        int p1 = atomicAdd(&g_cursor[d.y], 1);
        int p2 = atomicAdd(&g_cursor[d.z], 1);
        int p3 = atomicAdd(&g_cursor[d.w], 1);
        g_eid[p0] = e;
        g_eid[p1] = e + 1;
        g_eid[p2] = e + 2;
        g_eid[p3] = e + 3;
    }
}

// ---------------- tf32 helpers ----------------
__device__ __forceinline__ uint32_t f2tf32(float f) {
    uint32_t r;
    asm("cvt.rna.tf32.f32 %0, %1;" : "=r"(r) : "f"(f));
    return r;
}
__device__ __forceinline__ void mma_tf32(float& c0, float& c1, float& c2, float& c3,
                                         uint32_t a0, uint32_t a1, uint32_t a2, uint32_t a3,
                                         uint32_t b0, uint32_t b1) {
    asm volatile(
        "mma.sync.aligned.m16n8k8.row.col.f32.tf32.tf32.f32 "
        "{%0,%1,%2,%3}, {%4,%5,%6,%7}, {%8,%9}, {%0,%1,%2,%3};"
        : "+f"(c0), "+f"(c1), "+f"(c2), "+f"(c3)
        : "r"(a0), "r"(a1), "r"(a2), "r"(a3), "r"(b0), "r"(b1));
}

// ---------------- GEMM: C[128-tile,128] = A @ W  (tf32 mma.sync, fp16 out) --
#define PITCH 132
#define SM_WORDS (2 * DIM * PITCH)      // 33792 words = 135168 B
__global__ __launch_bounds__(256) void gemm_tc_kernel(const float* __restrict__ A,
                                                      const float* __restrict__ W,
                                                      __half* __restrict__ C) {
    extern __shared__ uint32_t smem[];
    uint32_t* sA = smem;
    uint32_t* sW = smem + DIM * PITCH;
    const int tid = threadIdx.x;
    const int wid = tid >> 5;
    const int lane = tid & 31;
    const int g = lane >> 2;            // group 0..7
    const int tg = lane & 3;            // thread-in-group 0..3
    const int r0 = blockIdx.x * 128;

    #pragma unroll
    for (int it = 0; it < 16; it++) {
        int idx = tid + it * 256;       // float4 idx 0..4095
        int r = idx >> 5;
        int c4 = idx & 31;
        float4 av = make_float4(0.f, 0.f, 0.f, 0.f);
        if (r0 + r < N_NODES)
            av = *(const float4*)(A + (size_t)(r0 + r) * DIM + c4 * 4);
        uint32_t* pa = sA + r * PITCH + c4 * 4;
        pa[0] = f2tf32(av.x); pa[1] = f2tf32(av.y);
        pa[2] = f2tf32(av.z); pa[3] = f2tf32(av.w);
        float4 wv = *(const float4*)(W + r * DIM + c4 * 4);
        uint32_t* pw = sW + r * PITCH + c4 * 4;
        pw[0] = f2tf32(wv.x); pw[1] = f2tf32(wv.y);
        pw[2] = f2tf32(wv.z); pw[3] = f2tf32(wv.w);
    }
    __syncthreads();

    float acc[16][4];
    #pragma unroll
    for (int nt = 0; nt < 16; nt++)
        #pragma unroll
        for (int q = 0; q < 4; q++) acc[nt][q] = 0.f;

    const uint32_t* aBase = sA + (wid * 16 + g) * PITCH;

    for (int ks = 0; ks < 16; ks++) {
        const int k0 = ks * 8;
        uint32_t a0 = aBase[k0 + tg];
        uint32_t a1 = aBase[8 * PITCH + k0 + tg];
        uint32_t a2 = aBase[k0 + tg + 4];
        uint32_t a3 = aBase[8 * PITCH + k0 + tg + 4];
        const uint32_t* b0p = sW + (k0 + tg) * PITCH + g;
        const uint32_t* b1p = sW + (k0 + tg + 4) * PITCH + g;
        #pragma unroll
        for (int nt = 0; nt < 16; nt++) {
            uint32_t b0 = b0p[nt * 8];
            uint32_t b1 = b1p[nt * 8];
            mma_tf32(acc[nt][0], acc[nt][1], acc[nt][2], acc[nt][3],
                     a0, a1, a2, a3, b0, b1);
        }
    }

    const int row0 = r0 + wid * 16 + g;
    const int row1 = row0 + 8;
    #pragma unroll
    for (int nt = 0; nt < 16; nt++) {
        int c = nt * 8 + tg * 2;
        if (row0 < N_NODES)
            *(__half2*)(C + (size_t)row0 * DIM + c) =
                __floats2half2_rn(acc[nt][0], acc[nt][1]);
        if (row1 < N_NODES)
            *(__half2*)(C + (size_t)row1 * DIM + c) =
                __floats2half2_rn(acc[nt][2], acc[nt][3]);
    }
}

// ---------------- aggregation: one WARP per node, fp16 gather, unroll 4 ----
__global__ __launch_bounds__(256) void agg_kernel(const __half* __restrict__ h,
                                                  const float* __restrict__ bias,
                                                  float* __restrict__ out,
                                                  const int* __restrict__ ei,
                                                  const float* __restrict__ ew,
                                                  int do_relu) {
    const int w = threadIdx.x >> 5;
    const int l = threadIdx.x & 31;
    const int i = blockIdx.x * 8 + w;
    if (i >= N_NODES) return;

    const float di = g_dis[i];
    const int beg = g_rowoff[i];
    const int end = g_rowoff[i + 1];

    float4 acc  = make_float4(0.f, 0.f, 0.f, 0.f);
    float4 acc2 = make_float4(0.f, 0.f, 0.f, 0.f);
    float4 acc3 = make_float4(0.f, 0.f, 0.f, 0.f);
    float4 acc4 = make_float4(0.f, 0.f, 0.f, 0.f);

    for (int base = beg; base < end; base += 32) {
        int n = end - base;
        if (n > 32) n = 32;
        int s = 0;
        float wt = 0.f;
        if (l < n) {
            int e = g_eid[base + l];
            s = ei[e];
            wt = g_dis[s] * ew[e] * di;
        }
        int j = 0;
        for (; j + 3 < n; j += 4) {
            int   s1 = __shfl_sync(0xffffffffu, s,  j);
            float w1 = __shfl_sync(0xffffffffu, wt, j);
            int   s2 = __shfl_sync(0xffffffffu, s,  j + 1);
            float w2 = __shfl_sync(0xffffffffu, wt, j + 1);
            int   s3 = __shfl_sync(0xffffffffu, s,  j + 2);
            float w3 = __shfl_sync(0xffffffffu, wt, j + 2);
            int   s4 = __shfl_sync(0xffffffffu, s,  j + 3);
            float w4 = __shfl_sync(0xffffffffu, wt, j + 3);
            uint2 r1 = *(const uint2*)(h + (size_t)s1 * DIM + l * 4);
            uint2 r2 = *(const uint2*)(h + (size_t)s2 * DIM + l * 4);
            uint2 r3 = *(const uint2*)(h + (size_t)s3 * DIM + l * 4);
            uint2 r4 = *(const uint2*)(h + (size_t)s4 * DIM + l * 4);
            float2 a1 = __half22float2(*(__half2*)&r1.x);
            float2 b1 = __half22float2(*(__half2*)&r1.y);
            float2 a2 = __half22float2(*(__half2*)&r2.x);
            float2 b2 = __half22float2(*(__half2*)&r2.y);
            float2 a3 = __half22float2(*(__half2*)&r3.x);
            float2 b3 = __half22float2(*(__half2*)&r3.y);
            float2 a4 = __half22float2(*(__half2*)&r4.x);
            float2 b4 = __half22float2(*(__half2*)&r4.y);
            acc.x  += a1.x * w1; acc.y  += a1.y * w1;
            acc.z  += b1.x * w1; acc.w  += b1.y * w1;
            acc2.x += a2.x * w2; acc2.y += a2.y * w2;
            acc2.z += b2.x * w2; acc2.w += b2.y * w2;
            acc3.x += a3.x * w3; acc3.y += a3.y * w3;
            acc3.z += b3.x * w3; acc3.w += b3.y * w3;
            acc4.x += a4.x * w4; acc4.y += a4.y * w4;
            acc4.z += b4.x * w4; acc4.w += b4.y * w4;
        }
        for (; j < n; j++) {
            int   s1 = __shfl_sync(0xffffffffu, s,  j);
            float w1 = __shfl_sync(0xffffffffu, wt, j);
            uint2 r1 = *(const uint2*)(h + (size_t)s1 * DIM + l * 4);
            float2 a1 = __half22float2(*(__half2*)&r1.x);
            float2 b1 = __half22float2(*(__half2*)&r1.y);
            acc.x += a1.x * w1; acc.y += a1.y * w1;
            acc.z += b1.x * w1; acc.w += b1.y * w1;
        }
    }

    acc.x += acc2.x + acc3.x + acc4.x;
    acc.y += acc2.y + acc3.y + acc4.y;
    acc.z += acc2.z + acc3.z + acc4.z;
    acc.w += acc2.w + acc3.w + acc4.w;

    const float dd = di * di;
    uint2 ri = *(const uint2*)(h + (size_t)i * DIM + l * 4);
    float2 hi0 = __half22float2(*(__half2*)&ri.x);
    float2 hi1 = __half22float2(*(__half2*)&ri.y);
    const float4 bv = *(const float4*)(bias + l * 4);
    acc.x += hi0.x * dd + bv.x;
    acc.y += hi0.y * dd + bv.y;
    acc.z += hi1.x * dd + bv.z;
    acc.w += hi1.y * dd + bv.w;
    if (do_relu) {
        acc.x = fmaxf(acc.x, 0.f);
        acc.y = fmaxf(acc.y, 0.f);
        acc.z = fmaxf(acc.z, 0.f);
        acc.w = fmaxf(acc.w, 0.f);
    }
    *(float4*)(out + (size_t)i * DIM + l * 4) = acc;
}

// ---------------- launch ----------------
extern "C" void kernel_launch(void* const* d_in, const int* in_sizes, int n_in,
                              void* d_out, int out_size) {
    const float* x  = (const float*)d_in[0];
    const int*   ei = (const int*)d_in[1];
    const float* ew = (const float*)d_in[2];
    const float* W1 = (const float*)d_in[3];
    const float* b1 = (const float*)d_in[4];
    const float* W2 = (const float*)d_in[5];
    const float* b2 = (const float*)d_in[6];
    float* out = (float*)d_out;

    __half* h_buf; cudaGetSymbolAddress((void**)&h_buf, g_h);
    float*  t_buf; cudaGetSymbolAddress((void**)&t_buf, g_t);

    static bool once = false;
    if (!once) {
        cudaFuncSetAttribute(gemm_tc_kernel,
                             cudaFuncAttributeMaxDynamicSharedMemorySize,
                             SM_WORDS * 4);
        once = true;
    }

    const int NB_N = (N_NODES + 255) / 256;
    const int NB_E4 = (N_EDGES / 4 + 255) / 256;
    const int NB_G = (N_NODES + 127) / 128;
    const int NB_A = (N_NODES + 7) / 8;

    // graph structure setup
    init_kernel<<<NB_N, 256>>>();
    count_kernel<<<NB_E4, 256>>>(ei, ew);
    scan1_kernel<<<NBS, 256>>>();      // also computes g_dis
    scan3_kernel<<<NBS, 256>>>();      // per-block offset from g_bsum (scan2 folded in)
    fill_kernel<<<NB_E4, 256>>>(ei);

    // layer 1
    gemm_tc_kernel<<<NB_G, 256, SM_WORDS * 4>>>(x, W1, h_buf);
    agg_kernel<<<NB_A, 256>>>(h_buf, b1, t_buf, ei, ew, 1);

    // layer 2
    gemm_tc_kernel<<<NB_G, 256, SM_WORDS * 4>>>(t_buf, W2, h_buf);
    agg_kernel<<<NB_A, 256>>>(h_buf, b2, out, ei, ew, 0);
}

// round 14
// speedup vs baseline: 1.0985x; 1.0985x over previous
#include <cuda_runtime.h>
#include <cuda_fp16.h>
#include <cstdint>

#define N_NODES 50000
#define N_EDGES 800000
#define DIM 128
#define NBS ((N_NODES + 255) / 256)   // 196 scan blocks

// ---------------- device scratch (no allocations allowed) ----------------
__device__ float  g_deg[N_NODES];
__device__ float  g_dis[N_NODES];
__device__ int    g_cnt[N_NODES];
__device__ int    g_pre[N_NODES];
__device__ int    g_bsum[NBS];
__device__ int    g_boff[NBS];
__device__ int    g_rowoff[N_NODES + 1];
__device__ int    g_cursor[N_NODES];
__device__ int    g_src[N_EDGES];     // CSR payload: source node
__device__ float  g_wt[N_EDGES];      // CSR payload: fully-normalized weight
__device__ __half g_h[N_NODES * DIM];
__device__ float  g_t[N_NODES * DIM];

// ---------------- setup kernels ----------------
__global__ void init_kernel() {
    int i = blockIdx.x * blockDim.x + threadIdx.x;
    if (i < N_NODES) { g_deg[i] = 0.f; g_cnt[i] = 0; }
}

__global__ void count_kernel(const int* __restrict__ ei,
                             const float* __restrict__ ew) {
    int e = blockIdx.x * blockDim.x + threadIdx.x;
    if (e < N_EDGES) {
        int d = ei[N_EDGES + e];        // dst
        atomicAdd(&g_deg[d], ew[e]);
        atomicAdd(&g_cnt[d], 1);
    }
}

__device__ __forceinline__ int block_scan_incl(int v, int* ws) {
    const int lane = threadIdx.x & 31;
    const int w = threadIdx.x >> 5;
    int incl = v;
    #pragma unroll
    for (int o = 1; o < 32; o <<= 1) {
        int t = __shfl_up_sync(0xffffffffu, incl, o);
        if (lane >= o) incl += t;
    }
    if (lane == 31) ws[w] = incl;
    __syncthreads();
    if (w == 0) {
        int nw = blockDim.x >> 5;
        int s = (lane < nw) ? ws[lane] : 0;
        #pragma unroll
        for (int o = 1; o < 32; o <<= 1) {
            int t = __shfl_up_sync(0xffffffffu, s, o);
            if (lane >= o) s += t;
        }
        if (lane < nw) ws[lane] = s;
    }
    __syncthreads();
    if (w > 0) incl += ws[w - 1];
    return incl;
}

// pass 1: per-block exclusive pre-scan + block sums; fused dis = rsqrt(deg+1)
__global__ __launch_bounds__(256) void scan1_kernel() {
    __shared__ int ws[8];
    int i = blockIdx.x * 256 + threadIdx.x;
    int v = (i < N_NODES) ? g_cnt[i] : 0;
    int incl = block_scan_incl(v, ws);
    if (i < N_NODES) g_pre[i] = incl - v;
    if (threadIdx.x == 255) g_bsum[blockIdx.x] = incl;
    if (i < N_NODES) g_dis[i] = rsqrtf(g_deg[i] + 1.0f);
}

// pass 2: scan the 196 block sums (single block)
__global__ __launch_bounds__(256) void scan2_kernel() {
    __shared__ int ws[8];
    int t = threadIdx.x;
    int v = (t < NBS) ? g_bsum[t] : 0;
    int incl = block_scan_incl(v, ws);
    if (t < NBS) g_boff[t] = incl - v;
}

// pass 3: add block offsets -> rowoff / cursor
__global__ __launch_bounds__(256) void scan3_kernel() {
    int i = blockIdx.x * 256 + threadIdx.x;
    if (i < N_NODES) {
        int r = g_pre[i] + g_boff[blockIdx.x];
        g_rowoff[i] = r;
        g_cursor[i] = r;
    }
    if (i == 0) g_rowoff[N_NODES] = N_EDGES;
}

// fill: scatter edge into CSR with fully-normalized weight payload
__global__ void fill_kernel(const int* __restrict__ ei,
                            const float* __restrict__ ew) {
    int e = blockIdx.x * blockDim.x + threadIdx.x;
    if (e < N_EDGES) {
        int s = ei[e];
        int d = ei[N_EDGES + e];
        float wt = g_dis[s] * ew[e] * g_dis[d];
        int pos = atomicAdd(&g_cursor[d], 1);
        g_src[pos] = s;
        g_wt[pos] = wt;
    }
}

// ---------------- tf32 helpers ----------------
__device__ __forceinline__ uint32_t f2tf32(float f) {
    uint32_t r;
    asm("cvt.rna.tf32.f32 %0, %1;" : "=r"(r) : "f"(f));
    return r;
}
__device__ __forceinline__ void mma_tf32(float& c0, float& c1, float& c2, float& c3,
                                         uint32_t a0, uint32_t a1, uint32_t a2, uint32_t a3,
                                         uint32_t b0, uint32_t b1) {
    asm volatile(
        "mma.sync.aligned.m16n8k8.row.col.f32.tf32.tf32.f32 "
        "{%0,%1,%2,%3}, {%4,%5,%6,%7}, {%8,%9}, {%0,%1,%2,%3};"
        : "+f"(c0), "+f"(c1), "+f"(c2), "+f"(c3)
        : "r"(a0), "r"(a1), "r"(a2), "r"(a3), "r"(b0), "r"(b1));
}

// ---------------- GEMM: C[128-tile,128] = A @ W  (tf32 mma.sync, fp16 out) --
#define PITCH 132
#define SM_WORDS (2 * DIM * PITCH)      // 33792 words = 135168 B
__global__ __launch_bounds__(256) void gemm_tc_kernel(const float* __restrict__ A,
                                                      const float* __restrict__ W,
                                                      __half* __restrict__ C) {
    extern __shared__ uint32_t smem[];
    uint32_t* sA = smem;
    uint32_t* sW = smem + DIM * PITCH;
    const int tid = threadIdx.x;
    const int wid = tid >> 5;
    const int lane = tid & 31;
    const int g = lane >> 2;            // group 0..7
    const int tg = lane & 3;            // thread-in-group 0..3
    const int r0 = blockIdx.x * 128;

    #pragma unroll
    for (int it = 0; it < 16; it++) {
        int idx = tid + it * 256;       // float4 idx 0..4095
        int r = idx >> 5;
        int c4 = idx & 31;
        float4 av = make_float4(0.f, 0.f, 0.f, 0.f);
        if (r0 + r < N_NODES)
            av = *(const float4*)(A + (size_t)(r0 + r) * DIM + c4 * 4);
        uint32_t* pa = sA + r * PITCH + c4 * 4;
        pa[0] = f2tf32(av.x); pa[1] = f2tf32(av.y);
        pa[2] = f2tf32(av.z); pa[3] = f2tf32(av.w);
        float4 wv = *(const float4*)(W + r * DIM + c4 * 4);
        uint32_t* pw = sW + r * PITCH + c4 * 4;
        pw[0] = f2tf32(wv.x); pw[1] = f2tf32(wv.y);
        pw[2] = f2tf32(wv.z); pw[3] = f2tf32(wv.w);
    }
    __syncthreads();

    float acc[16][4];
    #pragma unroll
    for (int nt = 0; nt < 16; nt++)
        #pragma unroll
        for (int q = 0; q < 4; q++) acc[nt][q] = 0.f;

    const uint32_t* aBase = sA + (wid * 16 + g) * PITCH;

    for (int ks = 0; ks < 16; ks++) {
        const int k0 = ks * 8;
        uint32_t a0 = aBase[k0 + tg];
        uint32_t a1 = aBase[8 * PITCH + k0 + tg];
        uint32_t a2 = aBase[k0 + tg + 4];
        uint32_t a3 = aBase[8 * PITCH + k0 + tg + 4];
        const uint32_t* b0p = sW + (k0 + tg) * PITCH + g;
        const uint32_t* b1p = sW + (k0 + tg + 4) * PITCH + g;
        #pragma unroll
        for (int nt = 0; nt < 16; nt++) {
            uint32_t b0 = b0p[nt * 8];
            uint32_t b1 = b1p[nt * 8];
            mma_tf32(acc[nt][0], acc[nt][1], acc[nt][2], acc[nt][3],
                     a0, a1, a2, a3, b0, b1);
        }
    }

    const int row0 = r0 + wid * 16 + g;
    const int row1 = row0 + 8;
    #pragma unroll
    for (int nt = 0; nt < 16; nt++) {
        int c = nt * 8 + tg * 2;
        if (row0 < N_NODES)
            *(__half2*)(C + (size_t)row0 * DIM + c) =
                __floats2half2_rn(acc[nt][0], acc[nt][1]);
        if (row1 < N_NODES)
            *(__half2*)(C + (size_t)row1 * DIM + c) =
                __floats2half2_rn(acc[nt][2], acc[nt][3]);
    }
}

// ---------------- aggregation: one WARP per node, fp16 gather ---------------
// Edge records come straight from the CSR payload (coalesced, pre-normalized).
__global__ __launch_bounds__(256) void agg_kernel(const __half* __restrict__ h,
                                                  const float* __restrict__ bias,
                                                  float* __restrict__ out,
                                                  int do_relu) {
    const int w = threadIdx.x >> 5;
    const int l = threadIdx.x & 31;
    const int i = blockIdx.x * 8 + w;
    if (i >= N_NODES) return;

    const float di = g_dis[i];
    const int beg = g_rowoff[i];
    const int end = g_rowoff[i + 1];

    float4 acc  = make_float4(0.f, 0.f, 0.f, 0.f);
    float4 acc2 = make_float4(0.f, 0.f, 0.f, 0.f);

    for (int base = beg; base < end; base += 32) {
        int n = end - base;
        if (n > 32) n = 32;
        int s = 0;
        float wt = 0.f;
        if (l < n) {
            s = g_src[base + l];
            wt = g_wt[base + l];
        }
        int j = 0;
        for (; j + 1 < n; j += 2) {
            int   s1 = __shfl_sync(0xffffffffu, s,  j);
            float w1 = __shfl_sync(0xffffffffu, wt, j);
            int   s2 = __shfl_sync(0xffffffffu, s,  j + 1);
            float w2 = __shfl_sync(0xffffffffu, wt, j + 1);
            uint2 r1 = *(const uint2*)(h + (size_t)s1 * DIM + l * 4);
            uint2 r2 = *(const uint2*)(h + (size_t)s2 * DIM + l * 4);
            float2 a1 = __half22float2(*(__half2*)&r1.x);
            float2 b1 = __half22float2(*(__half2*)&r1.y);
            float2 a2 = __half22float2(*(__half2*)&r2.x);
            float2 b2 = __half22float2(*(__half2*)&r2.y);
            acc.x  += a1.x * w1; acc.y  += a1.y * w1;
            acc.z  += b1.x * w1; acc.w  += b1.y * w1;
            acc2.x += a2.x * w2; acc2.y += a2.y * w2;
            acc2.z += b2.x * w2; acc2.w += b2.y * w2;
        }
        if (j < n) {
            int   s1 = __shfl_sync(0xffffffffu, s,  j);
            float w1 = __shfl_sync(0xffffffffu, wt, j);
            uint2 r1 = *(const uint2*)(h + (size_t)s1 * DIM + l * 4);
            float2 a1 = __half22float2(*(__half2*)&r1.x);
            float2 b1 = __half22float2(*(__half2*)&r1.y);
            acc.x += a1.x * w1; acc.y += a1.y * w1;
            acc.z += b1.x * w1; acc.w += b1.y * w1;
        }
    }

    acc.x += acc2.x; acc.y += acc2.y; acc.z += acc2.z; acc.w += acc2.w;

    const float dd = di * di;
    uint2 ri = *(const uint2*)(h + (size_t)i * DIM + l * 4);
    float2 hi0 = __half22float2(*(__half2*)&ri.x);
    float2 hi1 = __half22float2(*(__half2*)&ri.y);
    const float4 bv = *(const float4*)(bias + l * 4);
    acc.x += hi0.x * dd + bv.x;
    acc.y += hi0.y * dd + bv.y;
    acc.z += hi1.x * dd + bv.z;
    acc.w += hi1.y * dd + bv.w;
    if (do_relu) {
        acc.x = fmaxf(acc.x, 0.f);
        acc.y = fmaxf(acc.y, 0.f);
        acc.z = fmaxf(acc.z, 0.f);
        acc.w = fmaxf(acc.w, 0.f);
    }
    *(float4*)(out + (size_t)i * DIM + l * 4) = acc;
}

// ---------------- launch ----------------
extern "C" void kernel_launch(void* const* d_in, const int* in_sizes, int n_in,
                              void* d_out, int out_size) {
    const float* x  = (const float*)d_in[0];
    const int*   ei = (const int*)d_in[1];
    const float* ew = (const float*)d_in[2];
    const float* W1 = (const float*)d_in[3];
    const float* b1 = (const float*)d_in[4];
    const float* W2 = (const float*)d_in[5];
    const float* b2 = (const float*)d_in[6];
    float* out = (float*)d_out;

    __half* h_buf; cudaGetSymbolAddress((void**)&h_buf, g_h);
    float*  t_buf; cudaGetSymbolAddress((void**)&t_buf, g_t);

    static bool once = false;
    if (!once) {
        cudaFuncSetAttribute(gemm_tc_kernel,
                             cudaFuncAttributeMaxDynamicSharedMemorySize,
                             SM_WORDS * 4);
        once = true;
    }

    const int NB_N = (N_NODES + 255) / 256;
    const int NB_E = (N_EDGES + 255) / 256;
    const int NB_G = (N_NODES + 127) / 128;
    const int NB_A = (N_NODES + 7) / 8;

    // graph structure setup (R12-proven shape; fill now writes CSR payload)
    init_kernel<<<NB_N, 256>>>();
    count_kernel<<<NB_E, 256>>>(ei, ew);
    scan1_kernel<<<NBS, 256>>>();      // also computes g_dis
    scan2_kernel<<<1, 256>>>();
    scan3_kernel<<<NBS, 256>>>();
    fill_kernel<<<NB_E, 256>>>(ei, ew);

    // layer 1
    gemm_tc_kernel<<<NB_G, 256, SM_WORDS * 4>>>(x, W1, h_buf);
    agg_kernel<<<NB_A, 256>>>(h_buf, b1, t_buf, 1);

    // layer 2
    gemm_tc_kernel<<<NB_G, 256, SM_WORDS * 4>>>(t_buf, W2, h_buf);
    agg_kernel<<<NB_A, 256>>>(h_buf, b2, out, 0);
}

// round 15
// speedup vs baseline: 1.1641x; 1.0597x over previous
#include <cuda_runtime.h>
#include <cuda_fp16.h>
#include <cstdint>

#define N_NODES 50000
#define N_EDGES 800000
#define DIM 128
#define NBS ((N_NODES + 255) / 256)   // 196 scan blocks

// ---------------- device scratch (no allocations allowed) ----------------
__device__ float  g_deg[N_NODES];
__device__ float  g_dis[N_NODES];
__device__ int    g_cnt[N_NODES];
__device__ int    g_pre[N_NODES];
__device__ int    g_bsum[NBS];
__device__ int    g_boff[NBS];
__device__ int    g_rowoff[N_NODES + 1];
__device__ int    g_cursor[N_NODES];
__device__ int    g_src[N_EDGES];     // CSR payload: source node
__device__ float  g_wt[N_EDGES];      // CSR payload: fully-normalized weight
__device__ __half g_h[N_NODES * DIM];
__device__ float  g_t[N_NODES * DIM];

// ---------------- setup kernels ----------------
__global__ void init_kernel() {
    int i = blockIdx.x * blockDim.x + threadIdx.x;
    if (i < N_NODES) { g_deg[i] = 0.f; g_cnt[i] = 0; }
}

__global__ void count_kernel(const int* __restrict__ ei,
                             const float* __restrict__ ew) {
    int e = blockIdx.x * blockDim.x + threadIdx.x;
    if (e < N_EDGES) {
        int d = ei[N_EDGES + e];        // dst
        atomicAdd(&g_deg[d], ew[e]);
        atomicAdd(&g_cnt[d], 1);
    }
}

__device__ __forceinline__ int block_scan_incl(int v, int* ws) {
    const int lane = threadIdx.x & 31;
    const int w = threadIdx.x >> 5;
    int incl = v;
    #pragma unroll
    for (int o = 1; o < 32; o <<= 1) {
        int t = __shfl_up_sync(0xffffffffu, incl, o);
        if (lane >= o) incl += t;
    }
    if (lane == 31) ws[w] = incl;
    __syncthreads();
    if (w == 0) {
        int nw = blockDim.x >> 5;
        int s = (lane < nw) ? ws[lane] : 0;
        #pragma unroll
        for (int o = 1; o < 32; o <<= 1) {
            int t = __shfl_up_sync(0xffffffffu, s, o);
            if (lane >= o) s += t;
        }
        if (lane < nw) ws[lane] = s;
    }
    __syncthreads();
    if (w > 0) incl += ws[w - 1];
    return incl;
}

// pass 1: per-block exclusive pre-scan + block sums; fused dis = rsqrt(deg+1)
__global__ __launch_bounds__(256) void scan1_kernel() {
    __shared__ int ws[8];
    int i = blockIdx.x * 256 + threadIdx.x;
    int v = (i < N_NODES) ? g_cnt[i] : 0;
    int incl = block_scan_incl(v, ws);
    if (i < N_NODES) g_pre[i] = incl - v;
    if (threadIdx.x == 255) g_bsum[blockIdx.x] = incl;
    if (i < N_NODES) g_dis[i] = rsqrtf(g_deg[i] + 1.0f);
}

// pass 2: scan the 196 block sums (single block)
__global__ __launch_bounds__(256) void scan2_kernel() {
    __shared__ int ws[8];
    int t = threadIdx.x;
    int v = (t < NBS) ? g_bsum[t] : 0;
    int incl = block_scan_incl(v, ws);
    if (t < NBS) g_boff[t] = incl - v;
}

// pass 3: add block offsets -> rowoff / cursor
__global__ __launch_bounds__(256) void scan3_kernel() {
    int i = blockIdx.x * 256 + threadIdx.x;
    if (i < N_NODES) {
        int r = g_pre[i] + g_boff[blockIdx.x];
        g_rowoff[i] = r;
        g_cursor[i] = r;
    }
    if (i == 0) g_rowoff[N_NODES] = N_EDGES;
}

// fill: scatter edge into CSR with fully-normalized weight payload
__global__ void fill_kernel(const int* __restrict__ ei,
                            const float* __restrict__ ew) {
    int e = blockIdx.x * blockDim.x + threadIdx.x;
    if (e < N_EDGES) {
        int s = ei[e];
        int d = ei[N_EDGES + e];
        float wt = g_dis[s] * ew[e] * g_dis[d];
        int pos = atomicAdd(&g_cursor[d], 1);
        g_src[pos] = s;
        g_wt[pos] = wt;
    }
}

// ---------------- tf32 helpers ----------------
__device__ __forceinline__ uint32_t f2tf32(float f) {
    uint32_t r;
    asm("cvt.rna.tf32.f32 %0, %1;" : "=r"(r) : "f"(f));
    return r;
}
__device__ __forceinline__ void mma_tf32(float& c0, float& c1, float& c2, float& c3,
                                         uint32_t a0, uint32_t a1, uint32_t a2, uint32_t a3,
                                         uint32_t b0, uint32_t b1) {
    asm volatile(
        "mma.sync.aligned.m16n8k8.row.col.f32.tf32.tf32.f32 "
        "{%0,%1,%2,%3}, {%4,%5,%6,%7}, {%8,%9}, {%0,%1,%2,%3};"
        : "+f"(c0), "+f"(c1), "+f"(c2), "+f"(c3)
        : "r"(a0), "r"(a1), "r"(a2), "r"(a3), "r"(b0), "r"(b1));
}

// ---------------- GEMM: C[128-tile,128] = A @ W  (tf32 mma.sync, fp16 out) --
#define PITCH 132
#define SM_WORDS (2 * DIM * PITCH)      // 33792 words = 135168 B
__global__ __launch_bounds__(256) void gemm_tc_kernel(const float* __restrict__ A,
                                                      const float* __restrict__ W,
                                                      __half* __restrict__ C) {
    extern __shared__ uint32_t smem[];
    uint32_t* sA = smem;
    uint32_t* sW = smem + DIM * PITCH;
    const int tid = threadIdx.x;
    const int wid = tid >> 5;
    const int lane = tid & 31;
    const int g = lane >> 2;            // group 0..7
    const int tg = lane & 3;            // thread-in-group 0..3
    const int r0 = blockIdx.x * 128;

    #pragma unroll
    for (int it = 0; it < 16; it++) {
        int idx = tid + it * 256;       // float4 idx 0..4095
        int r = idx >> 5;
        int c4 = idx & 31;
        float4 av = make_float4(0.f, 0.f, 0.f, 0.f);
        if (r0 + r < N_NODES)
            av = *(const float4*)(A + (size_t)(r0 + r) * DIM + c4 * 4);
        uint32_t* pa = sA + r * PITCH + c4 * 4;
        pa[0] = f2tf32(av.x); pa[1] = f2tf32(av.y);
        pa[2] = f2tf32(av.z); pa[3] = f2tf32(av.w);
        float4 wv = *(const float4*)(W + r * DIM + c4 * 4);
        uint32_t* pw = sW + r * PITCH + c4 * 4;
        pw[0] = f2tf32(wv.x); pw[1] = f2tf32(wv.y);
        pw[2] = f2tf32(wv.z); pw[3] = f2tf32(wv.w);
    }
    __syncthreads();

    float acc[16][4];
    #pragma unroll
    for (int nt = 0; nt < 16; nt++)
        #pragma unroll
        for (int q = 0; q < 4; q++) acc[nt][q] = 0.f;

    const uint32_t* aBase = sA + (wid * 16 + g) * PITCH;

    for (int ks = 0; ks < 16; ks++) {
        const int k0 = ks * 8;
        uint32_t a0 = aBase[k0 + tg];
        uint32_t a1 = aBase[8 * PITCH + k0 + tg];
        uint32_t a2 = aBase[k0 + tg + 4];
        uint32_t a3 = aBase[8 * PITCH + k0 + tg + 4];
        const uint32_t* b0p = sW + (k0 + tg) * PITCH + g;
        const uint32_t* b1p = sW + (k0 + tg + 4) * PITCH + g;
        #pragma unroll
        for (int nt = 0; nt < 16; nt++) {
            uint32_t b0 = b0p[nt * 8];
            uint32_t b1 = b1p[nt * 8];
            mma_tf32(acc[nt][0], acc[nt][1], acc[nt][2], acc[nt][3],
                     a0, a1, a2, a3, b0, b1);
        }
    }

    const int row0 = r0 + wid * 16 + g;
    const int row1 = row0 + 8;
    #pragma unroll
    for (int nt = 0; nt < 16; nt++) {
        int c = nt * 8 + tg * 2;
        if (row0 < N_NODES)
            *(__half2*)(C + (size_t)row0 * DIM + c) =
                __floats2half2_rn(acc[nt][0], acc[nt][1]);
        if (row1 < N_NODES)
            *(__half2*)(C + (size_t)row1 * DIM + c) =
                __floats2half2_rn(acc[nt][2], acc[nt][3]);
    }
}

// ---------------- aggregation: one WARP per node, fp16 gather ---------------
__global__ __launch_bounds__(256) void agg_kernel(const __half* __restrict__ h,
                                                  const float* __restrict__ bias,
                                                  float* __restrict__ out,
                                                  int do_relu) {
    const int w = threadIdx.x >> 5;
    const int l = threadIdx.x & 31;
    const int i = blockIdx.x * 8 + w;
    if (i >= N_NODES) return;

    const float di = g_dis[i];
    const int beg = g_rowoff[i];
    const int end = g_rowoff[i + 1];

    float4 acc  = make_float4(0.f, 0.f, 0.f, 0.f);
    float4 acc2 = make_float4(0.f, 0.f, 0.f, 0.f);

    for (int base = beg; base < end; base += 32) {
        int n = end - base;
        if (n > 32) n = 32;
        int s = 0;
        float wt = 0.f;
        if (l < n) {
            s = g_src[base + l];
            wt = g_wt[base + l];
        }
        int j = 0;
        for (; j + 1 < n; j += 2) {
            int   s1 = __shfl_sync(0xffffffffu, s,  j);
            float w1 = __shfl_sync(0xffffffffu, wt, j);
            int   s2 = __shfl_sync(0xffffffffu, s,  j + 1);
            float w2 = __shfl_sync(0xffffffffu, wt, j + 1);
            uint2 r1 = *(const uint2*)(h + (size_t)s1 * DIM + l * 4);
            uint2 r2 = *(const uint2*)(h + (size_t)s2 * DIM + l * 4);
            float2 a1 = __half22float2(*(__half2*)&r1.x);
            float2 b1 = __half22float2(*(__half2*)&r1.y);
            float2 a2 = __half22float2(*(__half2*)&r2.x);
            float2 b2 = __half22float2(*(__half2*)&r2.y);
            acc.x  += a1.x * w1; acc.y  += a1.y * w1;
            acc.z  += b1.x * w1; acc.w  += b1.y * w1;
            acc2.x += a2.x * w2; acc2.y += a2.y * w2;
            acc2.z += b2.x * w2; acc2.w += b2.y * w2;
        }
        if (j < n) {
            int   s1 = __shfl_sync(0xffffffffu, s,  j);
            float w1 = __shfl_sync(0xffffffffu, wt, j);
            uint2 r1 = *(const uint2*)(h + (size_t)s1 * DIM + l * 4);
            float2 a1 = __half22float2(*(__half2*)&r1.x);
            float2 b1 = __half22float2(*(__half2*)&r1.y);
            acc.x += a1.x * w1; acc.y += a1.y * w1;
            acc.z += b1.x * w1; acc.w += b1.y * w1;
        }
    }

    acc.x += acc2.x; acc.y += acc2.y; acc.z += acc2.z; acc.w += acc2.w;

    const float dd = di * di;
    uint2 ri = *(const uint2*)(h + (size_t)i * DIM + l * 4);
    float2 hi0 = __half22float2(*(__half2*)&ri.x);
    float2 hi1 = __half22float2(*(__half2*)&ri.y);
    const float4 bv = *(const float4*)(bias + l * 4);
    acc.x += hi0.x * dd + bv.x;
    acc.y += hi0.y * dd + bv.y;
    acc.z += hi1.x * dd + bv.z;
    acc.w += hi1.y * dd + bv.w;
    if (do_relu) {
        acc.x = fmaxf(acc.x, 0.f);
        acc.y = fmaxf(acc.y, 0.f);
        acc.z = fmaxf(acc.z, 0.f);
        acc.w = fmaxf(acc.w, 0.f);
    }
    *(float4*)(out + (size_t)i * DIM + l * 4) = acc;
}

// ---------------- launch ----------------
extern "C" void kernel_launch(void* const* d_in, const int* in_sizes, int n_in,
                              void* d_out, int out_size) {
    const float* x  = (const float*)d_in[0];
    const int*   ei = (const int*)d_in[1];
    const float* ew = (const float*)d_in[2];
    const float* W1 = (const float*)d_in[3];
    const float* b1 = (const float*)d_in[4];
    const float* W2 = (const float*)d_in[5];
    const float* b2 = (const float*)d_in[6];
    float* out = (float*)d_out;

    __half* h_buf; cudaGetSymbolAddress((void**)&h_buf, g_h);
    float*  t_buf; cudaGetSymbolAddress((void**)&t_buf, g_t);

    static cudaStream_t s2 = nullptr;
    static cudaEvent_t ev_fork = nullptr, ev_join = nullptr;
    if (s2 == nullptr) {
        cudaStreamCreateWithFlags(&s2, cudaStreamNonBlocking);
        cudaEventCreateWithFlags(&ev_fork, cudaEventDisableTiming);
        cudaEventCreateWithFlags(&ev_join, cudaEventDisableTiming);
        cudaFuncSetAttribute(gemm_tc_kernel,
                             cudaFuncAttributeMaxDynamicSharedMemorySize,
                             SM_WORDS * 4);
    }

    const int NB_N = (N_NODES + 255) / 256;
    const int NB_E = (N_EDGES + 255) / 256;
    const int NB_G = (N_NODES + 127) / 128;
    const int NB_A = (N_NODES + 7) / 8;

    // fork: graph-structure setup runs concurrently with gemm1
    cudaEventRecord(ev_fork, 0);
    cudaStreamWaitEvent(s2, ev_fork, 0);
    init_kernel<<<NB_N, 256, 0, s2>>>();
    count_kernel<<<NB_E, 256, 0, s2>>>(ei, ew);
    scan1_kernel<<<NBS, 256, 0, s2>>>();      // also computes g_dis
    scan2_kernel<<<1, 256, 0, s2>>>();
    scan3_kernel<<<NBS, 256, 0, s2>>>();
    fill_kernel<<<NB_E, 256, 0, s2>>>(ei, ew);
    cudaEventRecord(ev_join, s2);

    // layer 1 GEMM (independent of graph structure) overlaps setup
    gemm_tc_kernel<<<NB_G, 256, SM_WORDS * 4>>>(x, W1, h_buf);

    // join: aggregation needs both
    cudaStreamWaitEvent(0, ev_join, 0);
    agg_kernel<<<NB_A, 256>>>(h_buf, b1, t_buf, 1);

    // layer 2
    gemm_tc_kernel<<<NB_G, 256, SM_WORDS * 4>>>(t_buf, W2, h_buf);
    agg_kernel<<<NB_A, 256>>>(h_buf, b2, out, 0);
}